// round 1
// baseline (speedup 1.0000x reference)
#include <cuda_runtime.h>
#include <cuda_bf16.h>

#define D 64
#define NMAX 100352          // >= 100000, padded

// Scratch (allocation-free rule: __device__ globals)
__device__ __align__(256) float g_z[(size_t)NMAX * D];
__device__ __align__(256) float g_msg[(size_t)NMAX * D];
__device__ __align__(256) float g_deg[NMAX];
__device__ __align__(256) float g_cnt[NMAX];
__device__ __align__(256) float g_inv[NMAX];

// ---------------------------------------------------------------------------
// deg/cnt init to 1.0 (self loops), then accumulate over edges, then inverse
// ---------------------------------------------------------------------------
__global__ void init_degcnt(float* __restrict__ deg, float* __restrict__ cnt, int n) {
    int i = blockIdx.x * blockDim.x + threadIdx.x;
    if (i < n) { deg[i] = 1.0f; cnt[i] = 1.0f; }
}

__global__ void accum_degcnt(const int* __restrict__ src, const int* __restrict__ dst,
                             float* __restrict__ deg, float* __restrict__ cnt, int E) {
    int e = blockIdx.x * blockDim.x + threadIdx.x;
    if (e < E) {
        atomicAdd(&deg[src[e]], 1.0f);
        atomicAdd(&cnt[dst[e]], 1.0f);
    }
}

__global__ void compute_inv(const float* __restrict__ deg, const float* __restrict__ cnt,
                            float* __restrict__ inv, int n) {
    int i = blockIdx.x * blockDim.x + threadIdx.x;
    if (i < n) inv[i] = 1.0f / (deg[i] * cnt[i]);
}

// ---------------------------------------------------------------------------
// GEMM + relu. One thread per output row, 64 fp32 accumulators.
// FUSE:  input row = in[row] - msg[row] * inv[row]   (high-pass combine)
// WMSG:  also write relu output into msg_out (self-loop seed for next scatter)
// ---------------------------------------------------------------------------
template <bool FUSE, bool WMSG>
__global__ __launch_bounds__(256) void gemm_relu(
    const float* __restrict__ in, const float* __restrict__ msg,
    const float* __restrict__ inv, const float* __restrict__ W,
    const float* __restrict__ bias, float* __restrict__ out,
    float* __restrict__ msg_out, int n)
{
    __shared__ __align__(16) float Ws[D * D];
    __shared__ float bs[D];
    int tid = threadIdx.x;
    #pragma unroll
    for (int i = tid; i < D * D; i += 256) Ws[i] = W[i];
    if (tid < D) bs[tid] = bias[tid];
    __syncthreads();

    int row = blockIdx.x * 256 + tid;
    if (row >= n) return;

    float acc[D];
    #pragma unroll
    for (int j = 0; j < D; j++) acc[j] = bs[j];

    float invr = 0.0f;
    if (FUSE) invr = inv[row];

    const float4* in4 = reinterpret_cast<const float4*>(in + (size_t)row * D);
    const float4* m4  = FUSE ? reinterpret_cast<const float4*>(msg + (size_t)row * D) : nullptr;

    #pragma unroll 4
    for (int k4 = 0; k4 < D / 4; k4++) {
        float4 av = in4[k4];
        if (FUSE) {
            float4 mv = m4[k4];
            av.x -= mv.x * invr;
            av.y -= mv.y * invr;
            av.z -= mv.z * invr;
            av.w -= mv.w * invr;
        }
        float a[4] = {av.x, av.y, av.z, av.w};
        #pragma unroll
        for (int kk = 0; kk < 4; kk++) {
            const float4* wrow = reinterpret_cast<const float4*>(&Ws[(k4 * 4 + kk) * D]);
            #pragma unroll
            for (int j4 = 0; j4 < D / 4; j4++) {
                float4 w = wrow[j4];            // smem broadcast, conflict-free
                acc[j4 * 4 + 0] += a[kk] * w.x;
                acc[j4 * 4 + 1] += a[kk] * w.y;
                acc[j4 * 4 + 2] += a[kk] * w.z;
                acc[j4 * 4 + 3] += a[kk] * w.w;
            }
        }
    }

    float4* o4  = reinterpret_cast<float4*>(out + (size_t)row * D);
    float4* mo4 = WMSG ? reinterpret_cast<float4*>(msg_out + (size_t)row * D) : nullptr;
    #pragma unroll
    for (int j4 = 0; j4 < D / 4; j4++) {
        float4 v;
        v.x = fmaxf(acc[j4 * 4 + 0], 0.0f);
        v.y = fmaxf(acc[j4 * 4 + 1], 0.0f);
        v.z = fmaxf(acc[j4 * 4 + 2], 0.0f);
        v.w = fmaxf(acc[j4 * 4 + 3], 0.0f);
        o4[j4] = v;
        if (WMSG) mo4[j4] = v;
    }
}

// ---------------------------------------------------------------------------
// Edge scatter: msg[dst] += z[src], 64 threads per edge (feature-parallel)
// ---------------------------------------------------------------------------
__global__ void scatter_add(const int* __restrict__ src, const int* __restrict__ dst,
                            const float* __restrict__ z, float* __restrict__ msg,
                            long long total /* = E*64 */) {
    long long idx = (long long)blockIdx.x * blockDim.x + threadIdx.x;
    if (idx >= total) return;
    int e = (int)(idx >> 6);
    int f = (int)(idx & 63);
    int s = src[e];
    int d = dst[e];
    atomicAdd(&msg[(size_t)d * D + f], z[(size_t)s * D + f]);
}

// ---------------------------------------------------------------------------
extern "C" void kernel_launch(void* const* d_in, const int* in_sizes, int n_in,
                              void* d_out, int out_size) {
    const float* x  = (const float*)d_in[0];
    const int*   ei = (const int*)d_in[1];     // jax silently downcasts int64->int32
    const float* W1 = (const float*)d_in[2];
    const float* b1 = (const float*)d_in[3];
    const float* W2 = (const float*)d_in[4];
    const float* b2 = (const float*)d_in[5];
    const float* W3 = (const float*)d_in[6];
    const float* b3 = (const float*)d_in[7];
    float* out = (float*)d_out;

    int n = in_sizes[0] / D;          // 100000
    int E = in_sizes[1] / 2;          // 1200000
    const int* src = ei;
    const int* dst = ei + E;

    float *z, *msg, *deg, *cnt, *inv;
    cudaGetSymbolAddress((void**)&z,   g_z);
    cudaGetSymbolAddress((void**)&msg, g_msg);
    cudaGetSymbolAddress((void**)&deg, g_deg);
    cudaGetSymbolAddress((void**)&cnt, g_cnt);
    cudaGetSymbolAddress((void**)&inv, g_inv);

    int tb = 256;
    int gb_n = (n + tb - 1) / tb;
    int gb_e = (E + tb - 1) / tb;
    long long total = (long long)E * D;
    int gb_s = (int)((total + tb - 1) / tb);
    int gb_rows = (n + 255) / 256;

    // degree / count / inverse (depends only on edges; recomputed each call)
    init_degcnt<<<gb_n, tb>>>(deg, cnt, n);
    accum_degcnt<<<gb_e, tb>>>(src, dst, deg, cnt, E);
    compute_inv<<<gb_n, tb>>>(deg, cnt, inv, n);

    // layer 1: z = relu(x@W1+b1); msg seeded with z (self loop)
    gemm_relu<false, true><<<gb_rows, 256>>>(x, nullptr, nullptr, W1, b1, z, msg, n);
    scatter_add<<<gb_s, tb>>>(src, dst, z, msg, total);

    // layer 2: in = z - msg*inv; z = relu(in@W2+b2); msg seeded with z
    gemm_relu<true, true><<<gb_rows, 256>>>(z, msg, inv, W2, b2, z, msg, n);
    scatter_add<<<gb_s, tb>>>(src, dst, z, msg, total);

    // layer 3: in = z - msg*inv; out = relu(in@W3+b3)
    gemm_relu<true, false><<<gb_rows, 256>>>(z, msg, inv, W3, b3, out, nullptr, n);
}

// round 2
// speedup vs baseline: 1.2735x; 1.2735x over previous
#include <cuda_runtime.h>
#include <cuda_bf16.h>

#define D 64
#define NMAX 100352          // >= 100000, padded

// Scratch (allocation-free rule: __device__ globals)
__device__ __align__(256) float g_z[(size_t)NMAX * D];
__device__ __align__(256) float g_msg[(size_t)NMAX * D];
__device__ __align__(256) float g_deg[NMAX];
__device__ __align__(256) float g_cnt[NMAX];
__device__ __align__(256) float g_inv[NMAX];

// ---------------------------------------------------------------------------
// deg/cnt init to 1.0 (self loops), accumulate over edges, then inverse
// ---------------------------------------------------------------------------
__global__ void init_degcnt(float* __restrict__ deg, float* __restrict__ cnt, int n) {
    int i = blockIdx.x * blockDim.x + threadIdx.x;
    if (i < n) { deg[i] = 1.0f; cnt[i] = 1.0f; }
}

__global__ void accum_degcnt(const int* __restrict__ src, const int* __restrict__ dst,
                             float* __restrict__ deg, float* __restrict__ cnt, int E) {
    int e = blockIdx.x * blockDim.x + threadIdx.x;
    if (e < E) {
        atomicAdd(&deg[src[e]], 1.0f);
        atomicAdd(&cnt[dst[e]], 1.0f);
    }
}

__global__ void compute_inv(const float* __restrict__ deg, const float* __restrict__ cnt,
                            float* __restrict__ inv, int n) {
    int i = blockIdx.x * blockDim.x + threadIdx.x;
    if (i < n) inv[i] = 1.0f / (deg[i] * cnt[i]);
}

// ---------------------------------------------------------------------------
// GEMM + relu: 2 threads per row, 32 output columns each (interleaved float4
// chunks so the two halves hit different smem banks). ~60 regs -> 4 blocks/SM.
// FUSE:  input row = in[row] - msg[row] * inv[row]   (high-pass combine)
// WMSG:  also write relu output into msg_out (self-loop seed for next scatter)
// ---------------------------------------------------------------------------
template <bool FUSE, bool WMSG>
__global__ __launch_bounds__(256) void gemm_relu(
    const float* __restrict__ in, const float* __restrict__ msg,
    const float* __restrict__ inv, const float* __restrict__ W,
    const float* __restrict__ bias, float* __restrict__ out,
    float* __restrict__ msg_out, int n)
{
    __shared__ __align__(16) float Ws[D * D];
    __shared__ __align__(16) float bs[D];
    int tid = threadIdx.x;
    #pragma unroll
    for (int i = tid; i < D * D; i += 256) Ws[i] = W[i];
    if (tid < D) bs[tid] = bias[tid];
    __syncthreads();

    int row = blockIdx.x * 128 + (tid >> 1);
    int h   = tid & 1;                 // column half: chunks (2*j4 + h)
    if (row >= n) return;

    float acc[32];
    #pragma unroll
    for (int j4 = 0; j4 < 8; j4++) {
        float4 bv = *reinterpret_cast<const float4*>(&bs[(2 * j4 + h) * 4]);
        acc[j4 * 4 + 0] = bv.x;
        acc[j4 * 4 + 1] = bv.y;
        acc[j4 * 4 + 2] = bv.z;
        acc[j4 * 4 + 3] = bv.w;
    }

    float invr = 0.0f;
    if (FUSE) invr = inv[row];

    const float4* in4 = reinterpret_cast<const float4*>(in + (size_t)row * D);
    const float4* m4  = FUSE ? reinterpret_cast<const float4*>(msg + (size_t)row * D) : nullptr;

    #pragma unroll
    for (int k4 = 0; k4 < D / 4; k4++) {
        float4 av = in4[k4];
        if (FUSE) {
            float4 mv = m4[k4];
            av.x -= mv.x * invr;
            av.y -= mv.y * invr;
            av.z -= mv.z * invr;
            av.w -= mv.w * invr;
        }
        float a[4] = {av.x, av.y, av.z, av.w};
        #pragma unroll
        for (int kk = 0; kk < 4; kk++) {
            const float* wrow = &Ws[(k4 * 4 + kk) * D];
            #pragma unroll
            for (int j4 = 0; j4 < 8; j4++) {
                float4 w = *reinterpret_cast<const float4*>(&wrow[(2 * j4 + h) * 4]);
                acc[j4 * 4 + 0] += a[kk] * w.x;
                acc[j4 * 4 + 1] += a[kk] * w.y;
                acc[j4 * 4 + 2] += a[kk] * w.z;
                acc[j4 * 4 + 3] += a[kk] * w.w;
            }
        }
    }

    float* orow = out + (size_t)row * D;
    float* mrow = WMSG ? (msg_out + (size_t)row * D) : nullptr;
    #pragma unroll
    for (int j4 = 0; j4 < 8; j4++) {
        float4 v;
        v.x = fmaxf(acc[j4 * 4 + 0], 0.0f);
        v.y = fmaxf(acc[j4 * 4 + 1], 0.0f);
        v.z = fmaxf(acc[j4 * 4 + 2], 0.0f);
        v.w = fmaxf(acc[j4 * 4 + 3], 0.0f);
        int c = (2 * j4 + h) * 4;
        *reinterpret_cast<float4*>(&orow[c]) = v;
        if (WMSG) *reinterpret_cast<float4*>(&mrow[c]) = v;
    }
}

// ---------------------------------------------------------------------------
// Edge scatter: msg[dst] += z[src], 16 threads per edge, red.global.add.v4.f32
// (sm_90+ vector reduction -> 4x fewer atomic instructions)
// ---------------------------------------------------------------------------
__global__ void scatter_add(const int* __restrict__ src, const int* __restrict__ dst,
                            const float* __restrict__ z, float* __restrict__ msg,
                            int E) {
    long long idx = (long long)blockIdx.x * blockDim.x + threadIdx.x;
    int e = (int)(idx >> 4);
    if (e >= E) return;
    int q = (int)(idx & 15);
    int s = src[e];
    int d = dst[e];
    float4 v = *reinterpret_cast<const float4*>(z + (size_t)s * D + q * 4);
    float* p = msg + (size_t)d * D + q * 4;
    asm volatile("red.global.add.v4.f32 [%0], {%1, %2, %3, %4};"
                 :: "l"(p), "f"(v.x), "f"(v.y), "f"(v.z), "f"(v.w)
                 : "memory");
}

// ---------------------------------------------------------------------------
extern "C" void kernel_launch(void* const* d_in, const int* in_sizes, int n_in,
                              void* d_out, int out_size) {
    const float* x  = (const float*)d_in[0];
    const int*   ei = (const int*)d_in[1];     // jax silently downcasts int64->int32
    const float* W1 = (const float*)d_in[2];
    const float* b1 = (const float*)d_in[3];
    const float* W2 = (const float*)d_in[4];
    const float* b2 = (const float*)d_in[5];
    const float* W3 = (const float*)d_in[6];
    const float* b3 = (const float*)d_in[7];
    float* out = (float*)d_out;

    int n = in_sizes[0] / D;          // 100000
    int E = in_sizes[1] / 2;          // 1200000
    const int* src = ei;
    const int* dst = ei + E;

    float *z, *msg, *deg, *cnt, *inv;
    cudaGetSymbolAddress((void**)&z,   g_z);
    cudaGetSymbolAddress((void**)&msg, g_msg);
    cudaGetSymbolAddress((void**)&deg, g_deg);
    cudaGetSymbolAddress((void**)&cnt, g_cnt);
    cudaGetSymbolAddress((void**)&inv, g_inv);

    int tb = 256;
    int gb_n = (n + tb - 1) / tb;
    int gb_e = (E + tb - 1) / tb;
    long long sthreads = (long long)E * 16;
    int gb_s = (int)((sthreads + tb - 1) / tb);
    int gb_rows = (n + 127) / 128;     // 128 rows per block (2 threads/row)

    // degree / count / inverse
    init_degcnt<<<gb_n, tb>>>(deg, cnt, n);
    accum_degcnt<<<gb_e, tb>>>(src, dst, deg, cnt, E);
    compute_inv<<<gb_n, tb>>>(deg, cnt, inv, n);

    // layer 1: z = relu(x@W1+b1); msg seeded with z (self loop)
    gemm_relu<false, true><<<gb_rows, 256>>>(x, nullptr, nullptr, W1, b1, z, msg, n);
    scatter_add<<<gb_s, tb>>>(src, dst, z, msg, E);

    // layer 2: in = z - msg*inv; z = relu(in@W2+b2); msg seeded with z
    gemm_relu<true, true><<<gb_rows, 256>>>(z, msg, inv, W2, b2, z, msg, n);
    scatter_add<<<gb_s, tb>>>(src, dst, z, msg, E);

    // layer 3: in = z - msg*inv; out = relu(in@W3+b3)
    gemm_relu<true, false><<<gb_rows, 256>>>(z, msg, inv, W3, b3, out, nullptr, n);
}

// round 4
// speedup vs baseline: 1.4394x; 1.1303x over previous
#include <cuda_runtime.h>
#include <cuda_bf16.h>

#define D 64
#define NMAX 100352          // >= 100000, padded
#define EMAX 1250000

// Scratch (allocation-free rule: __device__ globals)
__device__ __align__(256) float g_z[(size_t)NMAX * D];
__device__ __align__(256) float g_msg[(size_t)NMAX * D];
__device__ __align__(256) float g_deg[NMAX];     // out-degree incl self (float)
__device__ __align__(256) int   g_cin[NMAX];     // in-degree excl self
__device__ __align__(256) int   g_off[NMAX + 1]; // CSR offsets (by dst)
__device__ __align__(256) int   g_cur[NMAX];     // fill cursors
__device__ __align__(256) int   g_csr[EMAX];     // src ids grouped by dst
__device__ __align__(256) float g_inv[NMAX];

// ---------------------------------------------------------------------------
__global__ void init_hist(float* __restrict__ deg, int* __restrict__ cin, int n) {
    int i = blockIdx.x * blockDim.x + threadIdx.x;
    if (i < n) { deg[i] = 1.0f; cin[i] = 0; }
}

__global__ void accum_hist(const int* __restrict__ src, const int* __restrict__ dst,
                           float* __restrict__ deg, int* __restrict__ cin, int E) {
    int e = blockIdx.x * blockDim.x + threadIdx.x;
    if (e < E) {
        atomicAdd(&deg[src[e]], 1.0f);
        atomicAdd(&cin[dst[e]], 1);
    }
}

// Single-block exclusive scan over cin -> off, also off[n] and cur[i]=off[i]
__global__ __launch_bounds__(1024) void scan_off(const int* __restrict__ cin,
                                                 int* __restrict__ off,
                                                 int* __restrict__ cur, int n) {
    __shared__ int s[1024];
    int t = threadIdx.x;
    int chunk = (n + 1023) / 1024;
    int lo = t * chunk;
    int hi = min(n, lo + chunk);
    int sum = 0;
    for (int j = lo; j < hi; j++) sum += cin[j];
    s[t] = sum;
    __syncthreads();
    #pragma unroll
    for (int d = 1; d < 1024; d <<= 1) {
        int v = (t >= d) ? s[t - d] : 0;
        __syncthreads();
        s[t] += v;
        __syncthreads();
    }
    int run = s[t] - sum;             // exclusive prefix of this chunk
    for (int j = lo; j < hi; j++) {
        off[j] = run;
        cur[j] = run;
        run += cin[j];
    }
    if (t == 1023) off[n] = s[1023];
}

__global__ void fill_csr(const int* __restrict__ src, const int* __restrict__ dst,
                         int* __restrict__ cur, int* __restrict__ csr, int E) {
    int e = blockIdx.x * blockDim.x + threadIdx.x;
    if (e < E) {
        int p = atomicAdd(&cur[dst[e]], 1);
        csr[p] = src[e];
    }
}

__global__ void compute_inv(const float* __restrict__ deg, const int* __restrict__ cin,
                            float* __restrict__ inv, int n) {
    int i = blockIdx.x * blockDim.x + threadIdx.x;
    if (i < n) inv[i] = 1.0f / (deg[i] * (float)(cin[i] + 1));
}

// ---------------------------------------------------------------------------
// Gather: msg[i] = z[i] + sum_{j in in-neighbors(i)} z[j]   (zero atomics)
// 16 threads per node, float4 chunks. Reads L2-resident z rows.
// ---------------------------------------------------------------------------
__global__ __launch_bounds__(256) void gather(const int* __restrict__ off,
                                              const int* __restrict__ csr,
                                              const float* __restrict__ z,
                                              float* __restrict__ msg, int n) {
    long long idx = (long long)blockIdx.x * blockDim.x + threadIdx.x;
    int i = (int)(idx >> 4);
    if (i >= n) return;
    int q = (int)(idx & 15);

    const float4* z4 = reinterpret_cast<const float4*>(z);
    float4 acc = z4[(size_t)i * 16 + q];          // self loop
    int e = off[i], end = off[i + 1];

    // 2-deep software pipeline for MLP
    for (; e + 1 < end; e += 2) {
        int s0 = csr[e], s1 = csr[e + 1];
        float4 v0 = z4[(size_t)s0 * 16 + q];
        float4 v1 = z4[(size_t)s1 * 16 + q];
        acc.x += v0.x; acc.y += v0.y; acc.z += v0.z; acc.w += v0.w;
        acc.x += v1.x; acc.y += v1.y; acc.z += v1.z; acc.w += v1.w;
    }
    if (e < end) {
        int s0 = csr[e];
        float4 v0 = z4[(size_t)s0 * 16 + q];
        acc.x += v0.x; acc.y += v0.y; acc.z += v0.z; acc.w += v0.w;
    }
    reinterpret_cast<float4*>(msg)[(size_t)i * 16 + q] = acc;
}

// ---------------------------------------------------------------------------
// GEMM + relu: 1 thread per row, full-broadcast smem W loads, packed f32x2 FMA.
// FUSE: input row = in[row] - msg[row] * inv[row]
// ---------------------------------------------------------------------------
template <bool FUSE>
__global__ __launch_bounds__(256) void gemm_relu(
    const float* __restrict__ in, const float* __restrict__ msg,
    const float* __restrict__ inv, const float* __restrict__ W,
    const float* __restrict__ bias, float* __restrict__ out, int n)
{
    __shared__ __align__(16) float Ws[D * D];
    __shared__ __align__(16) float bs[D];
    int tid = threadIdx.x;
    #pragma unroll
    for (int i = tid; i < D * D; i += 256) Ws[i] = W[i];
    if (tid < D) bs[tid] = bias[tid];
    __syncthreads();

    int row = blockIdx.x * 256 + tid;
    if (row >= n) return;

    unsigned long long acc[32];
    #pragma unroll
    for (int j = 0; j < 32; j++) {
        asm("mov.b64 %0, {%1, %2};" : "=l"(acc[j]) : "f"(bs[2 * j]), "f"(bs[2 * j + 1]));
    }

    float invr = 0.0f;
    if (FUSE) invr = inv[row];

    const float4* in4 = reinterpret_cast<const float4*>(in + (size_t)row * D);
    const float4* m4  = FUSE ? reinterpret_cast<const float4*>(msg + (size_t)row * D) : nullptr;

    #pragma unroll
    for (int k4 = 0; k4 < D / 4; k4++) {
        float4 av = in4[k4];
        if (FUSE) {
            float4 mv = m4[k4];
            av.x -= mv.x * invr;
            av.y -= mv.y * invr;
            av.z -= mv.z * invr;
            av.w -= mv.w * invr;
        }
        float a[4] = {av.x, av.y, av.z, av.w};
        #pragma unroll
        for (int kk = 0; kk < 4; kk++) {
            unsigned long long ad;
            asm("mov.b64 %0, {%1, %1};" : "=l"(ad) : "f"(a[kk]));
            const ulonglong2* wr =
                reinterpret_cast<const ulonglong2*>(&Ws[(k4 * 4 + kk) * D]);
            #pragma unroll
            for (int j = 0; j < 16; j++) {
                ulonglong2 w = wr[j];   // LDS.128, full warp broadcast (1 wavefront)
                asm("fma.rn.f32x2 %0, %1, %2, %0;" : "+l"(acc[2 * j])     : "l"(ad), "l"(w.x));
                asm("fma.rn.f32x2 %0, %1, %2, %0;" : "+l"(acc[2 * j + 1]) : "l"(ad), "l"(w.y));
            }
        }
    }

    float o[D];
    #pragma unroll
    for (int j = 0; j < 32; j++) {
        float lo, hi;
        asm("mov.b64 {%0, %1}, %2;" : "=f"(lo), "=f"(hi) : "l"(acc[j]));
        o[2 * j]     = fmaxf(lo, 0.0f);
        o[2 * j + 1] = fmaxf(hi, 0.0f);
    }
    float4* o4 = reinterpret_cast<float4*>(out + (size_t)row * D);
    #pragma unroll
    for (int j4 = 0; j4 < D / 4; j4++) {
        o4[j4] = make_float4(o[4 * j4], o[4 * j4 + 1], o[4 * j4 + 2], o[4 * j4 + 3]);
    }
}

// ---------------------------------------------------------------------------
extern "C" void kernel_launch(void* const* d_in, const int* in_sizes, int n_in,
                              void* d_out, int out_size) {
    const float* x  = (const float*)d_in[0];
    const int*   ei = (const int*)d_in[1];     // jax silently downcasts int64->int32
    const float* W1 = (const float*)d_in[2];
    const float* b1 = (const float*)d_in[3];
    const float* W2 = (const float*)d_in[4];
    const float* b2 = (const float*)d_in[5];
    const float* W3 = (const float*)d_in[6];
    const float* b3 = (const float*)d_in[7];
    float* out = (float*)d_out;

    int n = in_sizes[0] / D;          // 100000
    int E = in_sizes[1] / 2;          // 1200000
    const int* src = ei;
    const int* dst = ei + E;

    float *z, *msg, *deg, *inv;
    int *cin, *off, *cur, *csr;
    cudaGetSymbolAddress((void**)&z,   g_z);
    cudaGetSymbolAddress((void**)&msg, g_msg);
    cudaGetSymbolAddress((void**)&deg, g_deg);
    cudaGetSymbolAddress((void**)&inv, g_inv);
    cudaGetSymbolAddress((void**)&cin, g_cin);
    cudaGetSymbolAddress((void**)&off, g_off);
    cudaGetSymbolAddress((void**)&cur, g_cur);
    cudaGetSymbolAddress((void**)&csr, g_csr);

    int tb = 256;
    int gb_n = (n + tb - 1) / tb;
    int gb_e = (E + tb - 1) / tb;
    int gb_rows = (n + 255) / 256;
    long long gthreads = (long long)n * 16;
    int gb_g = (int)((gthreads + tb - 1) / tb);

    // CSR build (once per call; serves both filters) + normalization
    init_hist<<<gb_n, tb>>>(deg, cin, n);
    accum_hist<<<gb_e, tb>>>(src, dst, deg, cin, E);
    scan_off<<<1, 1024>>>(cin, off, cur, n);
    fill_csr<<<gb_e, tb>>>(src, dst, cur, csr, E);
    compute_inv<<<gb_n, tb>>>(deg, cin, inv, n);

    // layer 1
    gemm_relu<false><<<gb_rows, 256>>>(x, nullptr, nullptr, W1, b1, z, n);
    gather<<<gb_g, tb>>>(off, csr, z, msg, n);

    // layer 2
    gemm_relu<true><<<gb_rows, 256>>>(z, msg, inv, W2, b2, z, n);
    gather<<<gb_g, tb>>>(off, csr, z, msg, n);

    // layer 3
    gemm_relu<true><<<gb_rows, 256>>>(z, msg, inv, W3, b3, out, n);
}

// round 5
// speedup vs baseline: 2.2659x; 1.5743x over previous
#include <cuda_runtime.h>
#include <cuda_bf16.h>

#define D 64
#define NMAX 100352          // >= 100000, padded
#define EMAX 1250000

// Scratch (allocation-free rule: __device__ globals)
__device__ __align__(256) float g_z[(size_t)NMAX * D];
__device__ __align__(256) float g_v[(size_t)NMAX * D];   // filtered input
__device__ __align__(256) float g_deg[NMAX];     // out-degree incl self (float)
__device__ __align__(256) int   g_cin[NMAX];     // in-degree excl self
__device__ __align__(256) int   g_off[NMAX + 1]; // CSR offsets (by dst)
__device__ __align__(256) int   g_cur[NMAX];     // fill cursors
__device__ __align__(256) int   g_csr[EMAX];     // src ids grouped by dst
__device__ __align__(256) float g_inv[NMAX];
__device__ int g_bsum[1024];
__device__ int g_bpre[1024];

// ---------------------------------------------------------------------------
__global__ void init_hist(float* __restrict__ deg, int* __restrict__ cin, int n) {
    int i = blockIdx.x * blockDim.x + threadIdx.x;
    if (i < n) { deg[i] = 1.0f; cin[i] = 0; }
}

__global__ void accum_hist(const int* __restrict__ src, const int* __restrict__ dst,
                           float* __restrict__ deg, int* __restrict__ cin, int E) {
    int e = blockIdx.x * blockDim.x + threadIdx.x;
    if (e < E) {
        atomicAdd(&deg[src[e]], 1.0f);
        atomicAdd(&cin[dst[e]], 1);
    }
}

// ---------------------------------------------------------------------------
// 3-phase multi-block exclusive scan of cin -> off (+ cur copy, + off[n]).
// 1024 elements per block, coalesced.
// ---------------------------------------------------------------------------
__global__ __launch_bounds__(256) void scan_phase1(const int* __restrict__ cin,
                                                   int* __restrict__ bsum, int n) {
    __shared__ int s[256];
    int b = blockIdx.x, t = threadIdx.x;
    int base = b * 1024 + t * 4;
    int sum = 0;
    #pragma unroll
    for (int k = 0; k < 4; k++) { int j = base + k; if (j < n) sum += cin[j]; }
    s[t] = sum; __syncthreads();
    #pragma unroll
    for (int d2 = 128; d2 > 0; d2 >>= 1) {
        if (t < d2) s[t] += s[t + d2];
        __syncthreads();
    }
    if (t == 0) bsum[b] = s[0];
}

__global__ __launch_bounds__(1024) void scan_phase2(const int* __restrict__ bsum,
                                                    int* __restrict__ bpre, int nb) {
    __shared__ int s[1024];
    int t = threadIdx.x;
    int v = (t < nb) ? bsum[t] : 0;
    s[t] = v; __syncthreads();
    #pragma unroll
    for (int d2 = 1; d2 < 1024; d2 <<= 1) {
        int x = (t >= d2) ? s[t - d2] : 0;
        __syncthreads();
        s[t] += x; __syncthreads();
    }
    if (t < nb) bpre[t] = s[t] - v;
}

__global__ __launch_bounds__(256) void scan_phase3(const int* __restrict__ cin,
                                                   const int* __restrict__ bpre,
                                                   int* __restrict__ off,
                                                   int* __restrict__ cur, int n) {
    __shared__ int s[256];
    int b = blockIdx.x, t = threadIdx.x;
    int base = b * 1024 + t * 4;
    int c[4]; int tot = 0;
    #pragma unroll
    for (int k = 0; k < 4; k++) {
        int j = base + k;
        c[k] = (j < n) ? cin[j] : 0;
        tot += c[k];
    }
    s[t] = tot; __syncthreads();
    #pragma unroll
    for (int d2 = 1; d2 < 256; d2 <<= 1) {
        int x = (t >= d2) ? s[t - d2] : 0;
        __syncthreads();
        s[t] += x; __syncthreads();
    }
    int run = bpre[b] + s[t] - tot;
    #pragma unroll
    for (int k = 0; k < 4; k++) {
        int j = base + k;
        if (j < n) {
            off[j] = run; cur[j] = run; run += c[k];
            if (j == n - 1) off[n] = run;
        }
    }
}

__global__ void fill_csr(const int* __restrict__ src, const int* __restrict__ dst,
                         int* __restrict__ cur, int* __restrict__ csr, int E) {
    int e = blockIdx.x * blockDim.x + threadIdx.x;
    if (e < E) {
        int p = atomicAdd(&cur[dst[e]], 1);
        csr[p] = src[e];
    }
}

__global__ void compute_inv(const float* __restrict__ deg, const int* __restrict__ cin,
                            float* __restrict__ inv, int n) {
    int i = blockIdx.x * blockDim.x + threadIdx.x;
    if (i < n) inv[i] = 1.0f / (deg[i] * (float)(cin[i] + 1));
}

// ---------------------------------------------------------------------------
// Gather + combine: one WARP per node; lanes cover the 64-float row as 32x8B.
// Each neighbor row load is one fully-coalesced 256B warp access.
// Writes v[i] = z[i] - (z[i] + sum_{j->i} z[j]) * inv[i]   (filtered input)
// ---------------------------------------------------------------------------
__global__ __launch_bounds__(256) void gather_combine(
    const int* __restrict__ off, const int* __restrict__ csr,
    const float* __restrict__ z, const float* __restrict__ inv,
    float* __restrict__ v, int n)
{
    int warp = (int)((blockIdx.x * 256 + threadIdx.x) >> 5);
    int lane = threadIdx.x & 31;
    if (warp >= n) return;
    int i = warp;

    const float2* z2 = reinterpret_cast<const float2*>(z);
    float2 self = z2[(size_t)i * 32 + lane];
    float2 acc = self;                         // self loop
    int e0 = off[i], end = off[i + 1];

    for (int base = e0; base < end; base += 32) {
        int m = min(32, end - base);
        int sidx = (base + lane < end) ? csr[base + lane] : 0;
        #pragma unroll 4
        for (int t = 0; t < m; t++) {
            int s = __shfl_sync(0xffffffff, sidx, t);
            float2 w = z2[(size_t)s * 32 + lane];
            acc.x += w.x; acc.y += w.y;
        }
    }
    float iv = inv[i];
    float2 o;
    o.x = self.x - acc.x * iv;
    o.y = self.y - acc.y * iv;
    reinterpret_cast<float2*>(v)[(size_t)i * 32 + lane] = o;
}

// ---------------------------------------------------------------------------
// GEMM + relu: 1 thread per row, full-broadcast smem W loads, packed f32x2 FMA.
// __launch_bounds__(256,2) caps regs at 128 -> 2 blocks/SM (16 warps).
// ---------------------------------------------------------------------------
__global__ __launch_bounds__(256, 2) void gemm_relu(
    const float* __restrict__ in, const float* __restrict__ W,
    const float* __restrict__ bias, float* __restrict__ out, int n)
{
    __shared__ __align__(16) float Ws[D * D];
    __shared__ __align__(16) float bs[D];
    int tid = threadIdx.x;
    #pragma unroll
    for (int i = tid; i < D * D; i += 256) Ws[i] = W[i];
    if (tid < D) bs[tid] = bias[tid];
    __syncthreads();

    int row = blockIdx.x * 256 + tid;
    if (row >= n) return;

    unsigned long long acc[32];
    #pragma unroll
    for (int j = 0; j < 32; j++) {
        asm("mov.b64 %0, {%1, %2};" : "=l"(acc[j]) : "f"(bs[2 * j]), "f"(bs[2 * j + 1]));
    }

    const float4* in4 = reinterpret_cast<const float4*>(in + (size_t)row * D);

    #pragma unroll 2
    for (int k4 = 0; k4 < D / 4; k4++) {
        float4 av = in4[k4];
        float a[4] = {av.x, av.y, av.z, av.w};
        #pragma unroll
        for (int kk = 0; kk < 4; kk++) {
            unsigned long long ad;
            asm("mov.b64 %0, {%1, %1};" : "=l"(ad) : "f"(a[kk]));
            const ulonglong2* wr =
                reinterpret_cast<const ulonglong2*>(&Ws[(k4 * 4 + kk) * D]);
            #pragma unroll
            for (int j = 0; j < 16; j++) {
                ulonglong2 w = wr[j];   // LDS.128, full warp broadcast
                asm("fma.rn.f32x2 %0, %1, %2, %0;" : "+l"(acc[2 * j])     : "l"(ad), "l"(w.x));
                asm("fma.rn.f32x2 %0, %1, %2, %0;" : "+l"(acc[2 * j + 1]) : "l"(ad), "l"(w.y));
            }
        }
    }

    float4* o4 = reinterpret_cast<float4*>(out + (size_t)row * D);
    #pragma unroll
    for (int j4 = 0; j4 < 16; j4++) {
        float lo, hi, lo2, hi2;
        asm("mov.b64 {%0, %1}, %2;" : "=f"(lo),  "=f"(hi)  : "l"(acc[2 * j4]));
        asm("mov.b64 {%0, %1}, %2;" : "=f"(lo2), "=f"(hi2) : "l"(acc[2 * j4 + 1]));
        o4[j4] = make_float4(fmaxf(lo, 0.0f), fmaxf(hi, 0.0f),
                             fmaxf(lo2, 0.0f), fmaxf(hi2, 0.0f));
    }
}

// ---------------------------------------------------------------------------
extern "C" void kernel_launch(void* const* d_in, const int* in_sizes, int n_in,
                              void* d_out, int out_size) {
    const float* x  = (const float*)d_in[0];
    const int*   ei = (const int*)d_in[1];     // jax silently downcasts int64->int32
    const float* W1 = (const float*)d_in[2];
    const float* b1 = (const float*)d_in[3];
    const float* W2 = (const float*)d_in[4];
    const float* b2 = (const float*)d_in[5];
    const float* W3 = (const float*)d_in[6];
    const float* b3 = (const float*)d_in[7];
    float* out = (float*)d_out;

    int n = in_sizes[0] / D;          // 100000
    int E = in_sizes[1] / 2;          // 1200000
    const int* src = ei;
    const int* dst = ei + E;

    float *z, *v, *deg, *inv;
    int *cin, *off, *cur, *csr, *bsum, *bpre;
    cudaGetSymbolAddress((void**)&z,    g_z);
    cudaGetSymbolAddress((void**)&v,    g_v);
    cudaGetSymbolAddress((void**)&deg,  g_deg);
    cudaGetSymbolAddress((void**)&inv,  g_inv);
    cudaGetSymbolAddress((void**)&cin,  g_cin);
    cudaGetSymbolAddress((void**)&off,  g_off);
    cudaGetSymbolAddress((void**)&cur,  g_cur);
    cudaGetSymbolAddress((void**)&csr,  g_csr);
    cudaGetSymbolAddress((void**)&bsum, g_bsum);
    cudaGetSymbolAddress((void**)&bpre, g_bpre);

    int tb = 256;
    int gb_n = (n + tb - 1) / tb;
    int gb_e = (E + tb - 1) / tb;
    int gb_rows = (n + 255) / 256;
    int nb = (n + 1023) / 1024;                 // scan blocks (98)
    int gb_w = (n * 32 + tb - 1) / tb;          // warp-per-node gather

    // CSR build (serves both filters) + normalization
    init_hist<<<gb_n, tb>>>(deg, cin, n);
    accum_hist<<<gb_e, tb>>>(src, dst, deg, cin, E);
    scan_phase1<<<nb, 256>>>(cin, bsum, n);
    scan_phase2<<<1, 1024>>>(bsum, bpre, nb);
    scan_phase3<<<nb, 256>>>(cin, bpre, off, cur, n);
    compute_inv<<<gb_n, tb>>>(deg, cin, inv, n);
    fill_csr<<<gb_e, tb>>>(src, dst, cur, csr, E);

    // layer 1
    gemm_relu<<<gb_rows, 256>>>(x, W1, b1, z, n);
    gather_combine<<<gb_w, tb>>>(off, csr, z, inv, v, n);

    // layer 2
    gemm_relu<<<gb_rows, 256>>>(v, W2, b2, z, n);
    gather_combine<<<gb_w, tb>>>(off, csr, z, inv, v, n);

    // layer 3
    gemm_relu<<<gb_rows, 256>>>(v, W3, b3, out, n);
}

// round 6
// speedup vs baseline: 2.4007x; 1.0595x over previous
#include <cuda_runtime.h>
#include <cuda_bf16.h>

#define D 64
#define NMAX 100352          // >= 100000, padded
#define EMAX 1250000

// Scratch (allocation-free rule: __device__ globals)
__device__ __align__(256) float g_z[(size_t)NMAX * D];
__device__ __align__(256) float g_v[(size_t)NMAX * D];   // filtered input
__device__ __align__(256) int   g_degi[NMAX];    // out-degree excl self (int)
__device__ __align__(256) int   g_cin[NMAX];     // in-degree excl self
__device__ __align__(256) int   g_off[NMAX + 1]; // CSR offsets (by dst)
__device__ __align__(256) int   g_cur[NMAX];     // fill cursors
__device__ __align__(256) int   g_csr[EMAX];     // src ids grouped by dst
__device__ __align__(256) float g_inv[NMAX];
__device__ int g_bsum[1024];
__device__ int g_bpre[1024];

// ---------------------------------------------------------------------------
__global__ void accum_hist(const int* __restrict__ src, const int* __restrict__ dst,
                           int* __restrict__ degi, int* __restrict__ cin, int E) {
    int e = blockIdx.x * blockDim.x + threadIdx.x;
    if (e < E) {
        atomicAdd(&degi[src[e]], 1);
        atomicAdd(&cin[dst[e]], 1);
    }
}

// ---------------------------------------------------------------------------
// 3-phase multi-block exclusive scan of cin -> off (+ cur copy, + off[n]),
// with inv[] computation folded into phase 3.
// ---------------------------------------------------------------------------
__global__ __launch_bounds__(256) void scan_phase1(const int* __restrict__ cin,
                                                   int* __restrict__ bsum, int n) {
    __shared__ int s[256];
    int b = blockIdx.x, t = threadIdx.x;
    int base = b * 1024 + t * 4;
    int sum = 0;
    #pragma unroll
    for (int k = 0; k < 4; k++) { int j = base + k; if (j < n) sum += cin[j]; }
    s[t] = sum; __syncthreads();
    #pragma unroll
    for (int d2 = 128; d2 > 0; d2 >>= 1) {
        if (t < d2) s[t] += s[t + d2];
        __syncthreads();
    }
    if (t == 0) bsum[b] = s[0];
}

__global__ __launch_bounds__(1024) void scan_phase2(const int* __restrict__ bsum,
                                                    int* __restrict__ bpre, int nb) {
    __shared__ int s[1024];
    int t = threadIdx.x;
    int v = (t < nb) ? bsum[t] : 0;
    s[t] = v; __syncthreads();
    #pragma unroll
    for (int d2 = 1; d2 < 1024; d2 <<= 1) {
        int x = (t >= d2) ? s[t - d2] : 0;
        __syncthreads();
        s[t] += x; __syncthreads();
    }
    if (t < nb) bpre[t] = s[t] - v;
}

__global__ __launch_bounds__(256) void scan_phase3(const int* __restrict__ cin,
                                                   const int* __restrict__ bpre,
                                                   const int* __restrict__ degi,
                                                   int* __restrict__ off,
                                                   int* __restrict__ cur,
                                                   float* __restrict__ inv, int n) {
    __shared__ int s[256];
    int b = blockIdx.x, t = threadIdx.x;
    int base = b * 1024 + t * 4;
    int c[4]; int tot = 0;
    #pragma unroll
    for (int k = 0; k < 4; k++) {
        int j = base + k;
        c[k] = (j < n) ? cin[j] : 0;
        tot += c[k];
    }
    s[t] = tot; __syncthreads();
    #pragma unroll
    for (int d2 = 1; d2 < 256; d2 <<= 1) {
        int x = (t >= d2) ? s[t - d2] : 0;
        __syncthreads();
        s[t] += x; __syncthreads();
    }
    int run = bpre[b] + s[t] - tot;
    #pragma unroll
    for (int k = 0; k < 4; k++) {
        int j = base + k;
        if (j < n) {
            off[j] = run; cur[j] = run; run += c[k];
            // deg = out-degree + self, cnt = in-degree + self
            inv[j] = 1.0f / ((float)(degi[j] + 1) * (float)(c[k] + 1));
            if (j == n - 1) off[n] = run;
        }
    }
}

__global__ void fill_csr(const int* __restrict__ src, const int* __restrict__ dst,
                         int* __restrict__ cur, int* __restrict__ csr, int E) {
    int e = blockIdx.x * blockDim.x + threadIdx.x;
    if (e < E) {
        int p = atomicAdd(&cur[dst[e]], 1);
        csr[p] = src[e];
    }
}

// ---------------------------------------------------------------------------
// Gather + combine: one WARP per node; lanes cover the 64-float row as 32x8B.
// Writes v[i] = z[i] - (z[i] + sum_{j->i} z[j]) * inv[i]   (filtered input)
// ---------------------------------------------------------------------------
__global__ __launch_bounds__(256) void gather_combine(
    const int* __restrict__ off, const int* __restrict__ csr,
    const float* __restrict__ z, const float* __restrict__ inv,
    float* __restrict__ v, int n)
{
    int warp = (int)((blockIdx.x * 256 + threadIdx.x) >> 5);
    int lane = threadIdx.x & 31;
    if (warp >= n) return;
    int i = warp;

    const float2* z2 = reinterpret_cast<const float2*>(z);
    float2 self = z2[(size_t)i * 32 + lane];
    float2 acc = self;                         // self loop
    int e0 = off[i], end = off[i + 1];

    for (int base = e0; base < end; base += 32) {
        int m = min(32, end - base);
        int sidx = (base + lane < end) ? csr[base + lane] : 0;
        #pragma unroll 4
        for (int t = 0; t < m; t++) {
            int s = __shfl_sync(0xffffffff, sidx, t);
            float2 w = z2[(size_t)s * 32 + lane];
            acc.x += w.x; acc.y += w.y;
        }
    }
    float iv = inv[i];
    float2 o;
    o.x = self.x - acc.x * iv;
    o.y = self.y - acc.y * iv;
    reinterpret_cast<float2*>(v)[(size_t)i * 32 + lane] = o;
}

// ---------------------------------------------------------------------------
// GEMM + relu: 1 thread per row, full-broadcast smem W loads, packed f32x2 FMA.
// __launch_bounds__(256,2) caps regs at 128 -> 2 blocks/SM (16 warps).
// ---------------------------------------------------------------------------
__global__ __launch_bounds__(256, 2) void gemm_relu(
    const float* __restrict__ in, const float* __restrict__ W,
    const float* __restrict__ bias, float* __restrict__ out, int n)
{
    __shared__ __align__(16) float Ws[D * D];
    __shared__ __align__(16) float bs[D];
    int tid = threadIdx.x;
    #pragma unroll
    for (int i = tid; i < D * D; i += 256) Ws[i] = W[i];
    if (tid < D) bs[tid] = bias[tid];
    __syncthreads();

    int row = blockIdx.x * 256 + tid;
    if (row >= n) return;

    unsigned long long acc[32];
    #pragma unroll
    for (int j = 0; j < 32; j++) {
        asm("mov.b64 %0, {%1, %2};" : "=l"(acc[j]) : "f"(bs[2 * j]), "f"(bs[2 * j + 1]));
    }

    const float4* in4 = reinterpret_cast<const float4*>(in + (size_t)row * D);

    #pragma unroll 2
    for (int k4 = 0; k4 < D / 4; k4++) {
        float4 av = in4[k4];
        float a[4] = {av.x, av.y, av.z, av.w};
        #pragma unroll
        for (int kk = 0; kk < 4; kk++) {
            unsigned long long ad;
            asm("mov.b64 %0, {%1, %1};" : "=l"(ad) : "f"(a[kk]));
            const ulonglong2* wr =
                reinterpret_cast<const ulonglong2*>(&Ws[(k4 * 4 + kk) * D]);
            #pragma unroll
            for (int j = 0; j < 16; j++) {
                ulonglong2 w = wr[j];   // LDS.128, full warp broadcast
                asm("fma.rn.f32x2 %0, %1, %2, %0;" : "+l"(acc[2 * j])     : "l"(ad), "l"(w.x));
                asm("fma.rn.f32x2 %0, %1, %2, %0;" : "+l"(acc[2 * j + 1]) : "l"(ad), "l"(w.y));
            }
        }
    }

    float4* o4 = reinterpret_cast<float4*>(out + (size_t)row * D);
    #pragma unroll
    for (int j4 = 0; j4 < 16; j4++) {
        float lo, hi, lo2, hi2;
        asm("mov.b64 {%0, %1}, %2;" : "=f"(lo),  "=f"(hi)  : "l"(acc[2 * j4]));
        asm("mov.b64 {%0, %1}, %2;" : "=f"(lo2), "=f"(hi2) : "l"(acc[2 * j4 + 1]));
        o4[j4] = make_float4(fmaxf(lo, 0.0f), fmaxf(hi, 0.0f),
                             fmaxf(lo2, 0.0f), fmaxf(hi2, 0.0f));
    }
}

// ---------------------------------------------------------------------------
extern "C" void kernel_launch(void* const* d_in, const int* in_sizes, int n_in,
                              void* d_out, int out_size) {
    const float* x  = (const float*)d_in[0];
    const int*   ei = (const int*)d_in[1];     // jax silently downcasts int64->int32
    const float* W1 = (const float*)d_in[2];
    const float* b1 = (const float*)d_in[3];
    const float* W2 = (const float*)d_in[4];
    const float* b2 = (const float*)d_in[5];
    const float* W3 = (const float*)d_in[6];
    const float* b3 = (const float*)d_in[7];
    float* out = (float*)d_out;

    int n = in_sizes[0] / D;          // 100000
    int E = in_sizes[1] / 2;          // 1200000
    const int* src = ei;
    const int* dst = ei + E;

    float *z, *v, *inv;
    int *degi, *cin, *off, *cur, *csr, *bsum, *bpre;
    cudaGetSymbolAddress((void**)&z,    g_z);
    cudaGetSymbolAddress((void**)&v,    g_v);
    cudaGetSymbolAddress((void**)&inv,  g_inv);
    cudaGetSymbolAddress((void**)&degi, g_degi);
    cudaGetSymbolAddress((void**)&cin,  g_cin);
    cudaGetSymbolAddress((void**)&off,  g_off);
    cudaGetSymbolAddress((void**)&cur,  g_cur);
    cudaGetSymbolAddress((void**)&csr,  g_csr);
    cudaGetSymbolAddress((void**)&bsum, g_bsum);
    cudaGetSymbolAddress((void**)&bpre, g_bpre);

    int tb = 256;
    int gb_e = (E + tb - 1) / tb;
    int gb_rows = (n + 255) / 256;
    int nb = (n + 1023) / 1024;                 // scan blocks (98)
    int gb_w = (n * 32 + tb - 1) / tb;          // warp-per-node gather

    // Fork a non-blocking side stream for the CSR chain; it is independent of
    // gemm1, so the graph runs them concurrently. (Stream/events leak — a
    // handful of host-side objects across the few kernel_launch calls; no
    // device memory involved.)
    cudaStream_t s2;
    cudaStreamCreateWithFlags(&s2, cudaStreamNonBlocking);
    cudaEvent_t eFork, eJoin;
    cudaEventCreateWithFlags(&eFork, cudaEventDisableTiming);
    cudaEventCreateWithFlags(&eJoin, cudaEventDisableTiming);

    cudaEventRecord(eFork, 0);                 // fork from capture (legacy) stream
    cudaStreamWaitEvent(s2, eFork, 0);

    // --- CSR build on s2 ---
    cudaMemsetAsync(degi, 0, n * sizeof(int), s2);
    cudaMemsetAsync(cin,  0, n * sizeof(int), s2);
    accum_hist<<<gb_e, tb, 0, s2>>>(src, dst, degi, cin, E);
    scan_phase1<<<nb, 256, 0, s2>>>(cin, bsum, n);
    scan_phase2<<<1, 1024, 0, s2>>>(bsum, bpre, nb);
    scan_phase3<<<nb, 256, 0, s2>>>(cin, bpre, degi, off, cur, inv, n);
    fill_csr<<<gb_e, tb, 0, s2>>>(src, dst, cur, csr, E);
    cudaEventRecord(eJoin, s2);

    // --- main chain on capture stream ---
    gemm_relu<<<gb_rows, 256>>>(x, W1, b1, z, n);          // independent of CSR

    cudaStreamWaitEvent(0, eJoin, 0);                      // join before gather
    gather_combine<<<gb_w, tb>>>(off, csr, z, inv, v, n);

    gemm_relu<<<gb_rows, 256>>>(v, W2, b2, z, n);
    gather_combine<<<gb_w, tb>>>(off, csr, z, inv, v, n);

    gemm_relu<<<gb_rows, 256>>>(v, W3, b3, out, n);
}

// round 11
// speedup vs baseline: 2.5110x; 1.0460x over previous
#include <cuda_runtime.h>
#include <cuda_bf16.h>

#define D 64
#define NMAX 100352          // >= 100000, padded
#define EMAX 1250000

// Scratch (allocation-free rule: __device__ globals)
__device__ __align__(256) float g_z[(size_t)NMAX * D];
__device__ __align__(256) float g_v[(size_t)NMAX * D];   // filtered input
__device__ __align__(256) int   g_degi[NMAX];    // out-degree excl self (int)
__device__ __align__(256) int   g_cin[NMAX];     // in-degree excl self
__device__ __align__(256) int   g_off[NMAX + 1]; // CSR offsets (by dst)
__device__ __align__(256) int   g_cur[NMAX];     // fill cursors
__device__ __align__(256) int   g_csr[EMAX];     // src ids grouped by dst
__device__ __align__(256) float g_inv[NMAX];
__device__ int g_bsum[1024];
__device__ int g_bpre[1024];

// ---------------------------------------------------------------------------
// Histogram: 2 edges per thread, int2 loads
// ---------------------------------------------------------------------------
__global__ void accum_hist(const int* __restrict__ src, const int* __restrict__ dst,
                           int* __restrict__ degi, int* __restrict__ cin, int E) {
    int e2 = blockIdx.x * blockDim.x + threadIdx.x;
    int e = e2 * 2;
    if (e + 1 < E) {
        int2 s = *reinterpret_cast<const int2*>(src + e);
        int2 d = *reinterpret_cast<const int2*>(dst + e);
        atomicAdd(&degi[s.x], 1);
        atomicAdd(&degi[s.y], 1);
        atomicAdd(&cin[d.x], 1);
        atomicAdd(&cin[d.y], 1);
    } else if (e < E) {
        atomicAdd(&degi[src[e]], 1);
        atomicAdd(&cin[dst[e]], 1);
    }
}

// ---------------------------------------------------------------------------
// 3-phase multi-block exclusive scan of cin -> off (+ cur copy, + off[n]),
// with inv[] computation folded into phase 3.
// ---------------------------------------------------------------------------
__global__ __launch_bounds__(256) void scan_phase1(const int* __restrict__ cin,
                                                   int* __restrict__ bsum, int n) {
    __shared__ int s[256];
    int b = blockIdx.x, t = threadIdx.x;
    int base = b * 1024 + t * 4;
    int sum = 0;
    #pragma unroll
    for (int k = 0; k < 4; k++) { int j = base + k; if (j < n) sum += cin[j]; }
    s[t] = sum; __syncthreads();
    #pragma unroll
    for (int d2 = 128; d2 > 0; d2 >>= 1) {
        if (t < d2) s[t] += s[t + d2];
        __syncthreads();
    }
    if (t == 0) bsum[b] = s[0];
}

// 1 block, 128 threads, shfl warp scan (nb <= 128)
__global__ __launch_bounds__(128) void scan_phase2(const int* __restrict__ bsum,
                                                   int* __restrict__ bpre, int nb) {
    __shared__ int ws[4];
    int t = threadIdx.x;
    int v = (t < nb) ? bsum[t] : 0;
    int x = v;
    #pragma unroll
    for (int d2 = 1; d2 < 32; d2 <<= 1) {
        int y = __shfl_up_sync(0xffffffff, x, d2);
        if ((t & 31) >= d2) x += y;
    }
    if ((t & 31) == 31) ws[t >> 5] = x;
    __syncthreads();
    int add = 0;
    int wid = t >> 5;
    #pragma unroll
    for (int i = 0; i < 3; i++) if (i < wid) add += ws[i];
    if (t < nb) bpre[t] = add + x - v;
}

__global__ __launch_bounds__(256) void scan_phase3(const int* __restrict__ cin,
                                                   const int* __restrict__ bpre,
                                                   const int* __restrict__ degi,
                                                   int* __restrict__ off,
                                                   int* __restrict__ cur,
                                                   float* __restrict__ inv, int n) {
    __shared__ int s[256];
    int b = blockIdx.x, t = threadIdx.x;
    int base = b * 1024 + t * 4;
    int c[4]; int tot = 0;
    #pragma unroll
    for (int k = 0; k < 4; k++) {
        int j = base + k;
        c[k] = (j < n) ? cin[j] : 0;
        tot += c[k];
    }
    s[t] = tot; __syncthreads();
    #pragma unroll
    for (int d2 = 1; d2 < 256; d2 <<= 1) {
        int x = (t >= d2) ? s[t - d2] : 0;
        __syncthreads();
        s[t] += x; __syncthreads();
    }
    int run = bpre[b] + s[t] - tot;
    #pragma unroll
    for (int k = 0; k < 4; k++) {
        int j = base + k;
        if (j < n) {
            off[j] = run; cur[j] = run; run += c[k];
            inv[j] = 1.0f / ((float)(degi[j] + 1) * (float)(c[k] + 1));
            if (j == n - 1) off[n] = run;
        }
    }
}

__global__ void fill_csr(const int* __restrict__ src, const int* __restrict__ dst,
                         int* __restrict__ cur, int* __restrict__ csr, int E) {
    int e2 = blockIdx.x * blockDim.x + threadIdx.x;
    int e = e2 * 2;
    if (e + 1 < E) {
        int2 s = *reinterpret_cast<const int2*>(src + e);
        int2 d = *reinterpret_cast<const int2*>(dst + e);
        int p0 = atomicAdd(&cur[d.x], 1);
        csr[p0] = s.x;
        int p1 = atomicAdd(&cur[d.y], 1);
        csr[p1] = s.y;
    } else if (e < E) {
        int p = atomicAdd(&cur[dst[e]], 1);
        csr[p] = src[e];
    }
}

// ---------------------------------------------------------------------------
// Gather + combine: one WARP per node; lanes cover the 64-float row as 32x8B.
// Writes v[i] = z[i] - (z[i] + sum_{j->i} z[j]) * inv[i]   (filtered input)
// ---------------------------------------------------------------------------
__global__ __launch_bounds__(256) void gather_combine(
    const int* __restrict__ off, const int* __restrict__ csr,
    const float* __restrict__ z, const float* __restrict__ inv,
    float* __restrict__ v, int n)
{
    int warp = (int)((blockIdx.x * 256 + threadIdx.x) >> 5);
    int lane = threadIdx.x & 31;
    if (warp >= n) return;
    int i = warp;

    const float2* z2 = reinterpret_cast<const float2*>(z);
    float2 self = z2[(size_t)i * 32 + lane];
    float2 acc = self;                         // self loop
    int e0 = off[i], end = off[i + 1];

    for (int base = e0; base < end; base += 32) {
        int m = min(32, end - base);
        int sidx = (base + lane < end) ? csr[base + lane] : 0;
        #pragma unroll 4
        for (int t = 0; t < m; t++) {
            int s = __shfl_sync(0xffffffff, sidx, t);
            float2 w = z2[(size_t)s * 32 + lane];
            acc.x += w.x; acc.y += w.y;
        }
    }
    float iv = inv[i];
    float2 o;
    o.x = self.x - acc.x * iv;
    o.y = self.y - acc.y * iv;
    reinterpret_cast<float2*>(v)[(size_t)i * 32 + lane] = o;
}

// ---------------------------------------------------------------------------
// GEMM + relu v2: warp-pair column split, 2 rows per thread.
// Warp pair (h=0,1): each warp does 64 rows x 32 cols. Every W LDS.128 is a
// full-warp broadcast (address depends only on k and h) and feeds TWO rows'
// FMAs -> per-row LDS wavefronts drop 4x vs v1.
// ---------------------------------------------------------------------------
__global__ __launch_bounds__(256, 2) void gemm_relu(
    const float* __restrict__ in, const float* __restrict__ W,
    const float* __restrict__ bias, float* __restrict__ out, int n)
{
    __shared__ __align__(16) float Ws[D * D];
    __shared__ __align__(16) float bs[D];
    int tid = threadIdx.x;
    #pragma unroll
    for (int i = tid; i < D * D; i += 256) Ws[i] = W[i];
    if (tid < D) bs[tid] = bias[tid];
    __syncthreads();

    int w    = tid >> 5;
    int lane = tid & 31;
    int p    = w >> 1;          // warp pair 0..3 -> 64 rows each
    int h    = w & 1;           // column half
    int rbase = blockIdx.x * 256 + p * 64;
    int r0 = rbase + lane;
    int r1 = rbase + lane + 32;
    int c0 = h * 32;
    if (r0 >= n) return;
    bool ok1 = (r1 < n);

    unsigned long long acc0[16], acc1[16];
    #pragma unroll
    for (int j = 0; j < 16; j++) {
        unsigned long long b2;
        asm("mov.b64 %0, {%1, %2};" : "=l"(b2) : "f"(bs[c0 + 2 * j]), "f"(bs[c0 + 2 * j + 1]));
        acc0[j] = b2;
        acc1[j] = b2;
    }

    const float4* i0 = reinterpret_cast<const float4*>(in + (size_t)r0 * D);
    const float4* i1 = reinterpret_cast<const float4*>(in + (size_t)r1 * D);

    #pragma unroll 2
    for (int k4 = 0; k4 < D / 4; k4++) {
        float4 a0 = i0[k4];
        float4 a1 = ok1 ? i1[k4] : make_float4(0.f, 0.f, 0.f, 0.f);
        float av0[4] = {a0.x, a0.y, a0.z, a0.w};
        float av1[4] = {a1.x, a1.y, a1.z, a1.w};
        #pragma unroll
        for (int kk = 0; kk < 4; kk++) {
            unsigned long long ad0, ad1;
            asm("mov.b64 %0, {%1, %1};" : "=l"(ad0) : "f"(av0[kk]));
            asm("mov.b64 %0, {%1, %1};" : "=l"(ad1) : "f"(av1[kk]));
            const ulonglong2* wr =
                reinterpret_cast<const ulonglong2*>(&Ws[(k4 * 4 + kk) * D + c0]);
            #pragma unroll
            for (int j = 0; j < 8; j++) {
                ulonglong2 wv = wr[j];   // LDS.128, full warp broadcast; feeds 2 rows
                asm("fma.rn.f32x2 %0, %1, %2, %0;" : "+l"(acc0[2 * j])     : "l"(ad0), "l"(wv.x));
                asm("fma.rn.f32x2 %0, %1, %2, %0;" : "+l"(acc0[2 * j + 1]) : "l"(ad0), "l"(wv.y));
                asm("fma.rn.f32x2 %0, %1, %2, %0;" : "+l"(acc1[2 * j])     : "l"(ad1), "l"(wv.x));
                asm("fma.rn.f32x2 %0, %1, %2, %0;" : "+l"(acc1[2 * j + 1]) : "l"(ad1), "l"(wv.y));
            }
        }
    }

    float4* o0 = reinterpret_cast<float4*>(out + (size_t)r0 * D + c0);
    #pragma unroll
    for (int j4 = 0; j4 < 8; j4++) {
        float lo, hi, lo2, hi2;
        asm("mov.b64 {%0, %1}, %2;" : "=f"(lo),  "=f"(hi)  : "l"(acc0[2 * j4]));
        asm("mov.b64 {%0, %1}, %2;" : "=f"(lo2), "=f"(hi2) : "l"(acc0[2 * j4 + 1]));
        o0[j4] = make_float4(fmaxf(lo, 0.0f), fmaxf(hi, 0.0f),
                             fmaxf(lo2, 0.0f), fmaxf(hi2, 0.0f));
    }
    if (ok1) {
        float4* o1 = reinterpret_cast<float4*>(out + (size_t)r1 * D + c0);
        #pragma unroll
        for (int j4 = 0; j4 < 8; j4++) {
            float lo, hi, lo2, hi2;
            asm("mov.b64 {%0, %1}, %2;" : "=f"(lo),  "=f"(hi)  : "l"(acc1[2 * j4]));
            asm("mov.b64 {%0, %1}, %2;" : "=f"(lo2), "=f"(hi2) : "l"(acc1[2 * j4 + 1]));
            o1[j4] = make_float4(fmaxf(lo, 0.0f), fmaxf(hi, 0.0f),
                                 fmaxf(lo2, 0.0f), fmaxf(hi2, 0.0f));
        }
    }
}

// ---------------------------------------------------------------------------
extern "C" void kernel_launch(void* const* d_in, const int* in_sizes, int n_in,
                              void* d_out, int out_size) {
    const float* x  = (const float*)d_in[0];
    const int*   ei = (const int*)d_in[1];     // jax silently downcasts int64->int32
    const float* W1 = (const float*)d_in[2];
    const float* b1 = (const float*)d_in[3];
    const float* W2 = (const float*)d_in[4];
    const float* b2 = (const float*)d_in[5];
    const float* W3 = (const float*)d_in[6];
    const float* b3 = (const float*)d_in[7];
    float* out = (float*)d_out;

    int n = in_sizes[0] / D;          // 100000
    int E = in_sizes[1] / 2;          // 1200000
    const int* src = ei;
    const int* dst = ei + E;

    float *z, *v, *inv;
    int *degi, *cin, *off, *cur, *csr, *bsum, *bpre;
    cudaGetSymbolAddress((void**)&z,    g_z);
    cudaGetSymbolAddress((void**)&v,    g_v);
    cudaGetSymbolAddress((void**)&inv,  g_inv);
    cudaGetSymbolAddress((void**)&degi, g_degi);
    cudaGetSymbolAddress((void**)&cin,  g_cin);
    cudaGetSymbolAddress((void**)&off,  g_off);
    cudaGetSymbolAddress((void**)&cur,  g_cur);
    cudaGetSymbolAddress((void**)&csr,  g_csr);
    cudaGetSymbolAddress((void**)&bsum, g_bsum);
    cudaGetSymbolAddress((void**)&bpre, g_bpre);

    int tb = 256;
    int gb_e2 = ((E + 1) / 2 + tb - 1) / tb;    // 2 edges per thread
    int gb_rows = (n + 255) / 256;
    int nb = (n + 1023) / 1024;                 // scan blocks (98)
    int gb_w = (n * 32 + tb - 1) / tb;          // warp-per-node gather

    // Fork a non-blocking side stream for the CSR chain (independent of gemm1).
    cudaStream_t s2;
    cudaStreamCreateWithFlags(&s2, cudaStreamNonBlocking);
    cudaEvent_t eFork, eJoin;
    cudaEventCreateWithFlags(&eFork, cudaEventDisableTiming);
    cudaEventCreateWithFlags(&eJoin, cudaEventDisableTiming);

    cudaEventRecord(eFork, 0);
    cudaStreamWaitEvent(s2, eFork, 0);

    // --- CSR build on s2 ---
    cudaMemsetAsync(degi, 0, n * sizeof(int), s2);
    cudaMemsetAsync(cin,  0, n * sizeof(int), s2);
    accum_hist<<<gb_e2, tb, 0, s2>>>(src, dst, degi, cin, E);
    scan_phase1<<<nb, 256, 0, s2>>>(cin, bsum, n);
    scan_phase2<<<1, 128, 0, s2>>>(bsum, bpre, nb);
    scan_phase3<<<nb, 256, 0, s2>>>(cin, bpre, degi, off, cur, inv, n);
    fill_csr<<<gb_e2, tb, 0, s2>>>(src, dst, cur, csr, E);
    cudaEventRecord(eJoin, s2);

    // --- main chain on capture stream ---
    gemm_relu<<<gb_rows, 256>>>(x, W1, b1, z, n);          // independent of CSR

    cudaStreamWaitEvent(0, eJoin, 0);                      // join before gather
    gather_combine<<<gb_w, tb>>>(off, csr, z, inv, v, n);

    gemm_relu<<<gb_rows, 256>>>(v, W2, b2, z, n);
    gather_combine<<<gb_w, tb>>>(off, csr, z, inv, v, n);

    gemm_relu<<<gb_rows, 256>>>(v, W3, b3, out, n);
}